// round 1
// baseline (speedup 1.0000x reference)
#include <cuda_runtime.h>
#include <cuda_bf16.h>
#include <math.h>

// Eikonal loss: Sobel gradient magnitude of pred_dist (edge-padded),
// violation = |mag - 1|, masked mean over reachable > 0.5.
// Shapes: (B, 1, H, W) = (64, 1, 512, 512) fp32. Output: 1 fp32 scalar.

#define H 512
#define W 512
#define W4 (W / 4)

__device__ float g_sum;
__device__ float g_cnt;

__global__ void eik_init_kernel() {
    g_sum = 0.0f;
    g_cnt = 0.0f;
}

__global__ void __launch_bounds__(256) eik_main_kernel(
    const float* __restrict__ pred,
    const float* __restrict__ reach,
    int nGroups)  // B * H * W4
{
    float lsum = 0.0f;
    float lcnt = 0.0f;

    const int stride = gridDim.x * blockDim.x;
    for (int g = blockIdx.x * blockDim.x + threadIdx.x; g < nGroups; g += stride) {
        const int b    = g / (H * W4);
        const int rem  = g - b * (H * W4);
        const int y    = rem / W4;
        const int x4   = (rem - y * W4) * 4;

        const size_t base = (size_t)b * H * W;
        const float* rowM = pred + base + (size_t)y * W;
        const int yT = (y > 0)     ? (y - 1) : 0;
        const int yB = (y < H - 1) ? (y + 1) : (H - 1);
        const float* rowT = pred + base + (size_t)yT * W;
        const float* rowB = pred + base + (size_t)yB * W;

        const int xl = (x4 > 0) ? (x4 - 1) : 0;
        const int xr = (x4 + 4 < W) ? (x4 + 4) : (W - 1);

        // Six-wide window per row: columns x4-1 .. x4+4 (edge-clamped)
        float4 vT = *(const float4*)(rowT + x4);
        float4 vM = *(const float4*)(rowM + x4);
        float4 vB = *(const float4*)(rowB + x4);

        float t[6], m[6], bm[6];
        t[0]  = __ldg(rowT + xl); t[1] = vT.x; t[2] = vT.y; t[3] = vT.z; t[4] = vT.w; t[5]  = __ldg(rowT + xr);
        m[0]  = __ldg(rowM + xl); m[1] = vM.x; m[2] = vM.y; m[3] = vM.z; m[4] = vM.w; m[5]  = __ldg(rowM + xr);
        bm[0] = __ldg(rowB + xl); bm[1] = vB.x; bm[2] = vB.y; bm[3] = vB.z; bm[4] = vB.w; bm[5] = __ldg(rowB + xr);

        float4 rr = *(const float4*)(reach + base + (size_t)y * W + x4);
        const float rv[4] = {rr.x, rr.y, rr.z, rr.w};

        #pragma unroll
        for (int i = 0; i < 4; i++) {
            // cross-correlation with Sobel/8 (XLA conv does no kernel flip)
            float gx = (t[i + 2] - t[i]) + 2.0f * (m[i + 2] - m[i]) + (bm[i + 2] - bm[i]);
            float gy = (bm[i] + 2.0f * bm[i + 1] + bm[i + 2]) - (t[i] + 2.0f * t[i + 1] + t[i + 2]);
            gx *= 0.125f;
            gy *= 0.125f;
            float mag = sqrtf(fmaf(gx, gx, fmaf(gy, gy, 1e-8f)));
            float viol = fabsf(mag - 1.0f);
            if (rv[i] > 0.5f) {
                lsum += viol;
                lcnt += 1.0f;
            }
        }
    }

    // ---- block reduction ----
    #pragma unroll
    for (int off = 16; off > 0; off >>= 1) {
        lsum += __shfl_down_sync(0xFFFFFFFFu, lsum, off);
        lcnt += __shfl_down_sync(0xFFFFFFFFu, lcnt, off);
    }

    __shared__ float s_sum[8];
    __shared__ float s_cnt[8];
    const int lane = threadIdx.x & 31;
    const int wid  = threadIdx.x >> 5;
    if (lane == 0) { s_sum[wid] = lsum; s_cnt[wid] = lcnt; }
    __syncthreads();

    if (wid == 0) {
        lsum = (lane < 8) ? s_sum[lane] : 0.0f;
        lcnt = (lane < 8) ? s_cnt[lane] : 0.0f;
        #pragma unroll
        for (int off = 4; off > 0; off >>= 1) {
            lsum += __shfl_down_sync(0xFFFFFFFFu, lsum, off);
            lcnt += __shfl_down_sync(0xFFFFFFFFu, lcnt, off);
        }
        if (lane == 0) {
            atomicAdd(&g_sum, lsum);
            atomicAdd(&g_cnt, lcnt);
        }
    }
}

__global__ void eik_final_kernel(float* __restrict__ out) {
    out[0] = g_sum / fmaxf(g_cnt, 1.0f);
}

extern "C" void kernel_launch(void* const* d_in, const int* in_sizes, int n_in,
                              void* d_out, int out_size) {
    const float* pred  = (const float*)d_in[0];
    const float* reach = (const float*)d_in[1];
    float* out = (float*)d_out;

    const int total   = in_sizes[0];          // B*H*W
    const int nGroups = total / 4;            // float4 groups

    eik_init_kernel<<<1, 1>>>();

    const int threads = 256;
    int blocks = 148 * 16;                    // grid-stride, ~2.4K blocks
    int maxBlocks = (nGroups + threads - 1) / threads;
    if (blocks > maxBlocks) blocks = maxBlocks;
    eik_main_kernel<<<blocks, threads>>>(pred, reach, nGroups);

    eik_final_kernel<<<1, 1>>>(out);
}

// round 2
// speedup vs baseline: 1.1004x; 1.1004x over previous
#include <cuda_runtime.h>
#include <cuda_bf16.h>
#include <math.h>

// Eikonal loss, single fused kernel.
// Sobel/8 gradient magnitude of pred (edge-padded), |mag-1|, masked mean over reach>0.5.
// (B,1,H,W) = (64,1,512,512) fp32 -> 1 fp32 scalar.

#define H 512
#define W 512
#define W4 (W / 4)
#define ROWS 16               // rows per thread strip
#define STRIPS (H / ROWS)     // 32
#define THREADS 256
#define MAX_BLOCKS 4096

__device__ float2 g_part[MAX_BLOCKS];
__device__ unsigned int g_ticket;   // zero-init at load; last block resets to 0

__global__ void __launch_bounds__(THREADS) eik_fused_kernel(
    const float* __restrict__ pred,
    const float* __restrict__ reach,
    float* __restrict__ out,
    int nBlocks)
{
    const int gtid = blockIdx.x * THREADS + threadIdx.x;
    // mapping: fastest dim x4 (128), then strip (32), then batch (64)
    const int x4i   = gtid & (W4 - 1);
    const int sg    = gtid >> 7;            // global strip id: b*STRIPS + strip
    const int b     = sg / STRIPS;
    const int strip = sg - b * STRIPS;

    const int x  = x4i * 4;
    const int xl = (x > 0) ? (x - 1) : 0;
    const int xr = (x + 4 < W) ? (x + 4) : (W - 1);

    const size_t base = (size_t)b * H * W;
    const float* p = pred + base;
    const float* r = reach + base;

    const int y0 = strip * ROWS;

    float t[6], m[6], bt[6];

    // initial rows: top = clamp(y0-1), mid = y0
    {
        const int yT = (y0 > 0) ? (y0 - 1) : 0;
        const float* rowT = p + (size_t)yT * W;
        const float* rowM = p + (size_t)y0 * W;
        float4 vT = *(const float4*)(rowT + x);
        float4 vM = *(const float4*)(rowM + x);
        t[0] = __ldg(rowT + xl); t[1] = vT.x; t[2] = vT.y; t[3] = vT.z; t[4] = vT.w; t[5] = __ldg(rowT + xr);
        m[0] = __ldg(rowM + xl); m[1] = vM.x; m[2] = vM.y; m[3] = vM.z; m[4] = vM.w; m[5] = __ldg(rowM + xr);
    }

    float lsum = 0.0f;
    float lcnt = 0.0f;

    #pragma unroll
    for (int i = 0; i < ROWS; i++) {
        const int y  = y0 + i;
        const int yB = (y < H - 1) ? (y + 1) : (H - 1);
        const float* rowB = p + (size_t)yB * W;
        float4 vB = *(const float4*)(rowB + x);
        bt[0] = __ldg(rowB + xl); bt[1] = vB.x; bt[2] = vB.y; bt[3] = vB.z; bt[4] = vB.w; bt[5] = __ldg(rowB + xr);

        float4 rr = *(const float4*)(r + (size_t)y * W + x);
        const float rv[4] = {rr.x, rr.y, rr.z, rr.w};

        #pragma unroll
        for (int j = 0; j < 4; j++) {
            // cross-correlation with Sobel/8 (no kernel flip in XLA conv)
            float gx = (t[j + 2] - t[j]) + 2.0f * (m[j + 2] - m[j]) + (bt[j + 2] - bt[j]);
            float gy = (bt[j] + 2.0f * bt[j + 1] + bt[j + 2]) - (t[j] + 2.0f * t[j + 1] + t[j + 2]);
            gx *= 0.125f;
            gy *= 0.125f;
            float mag  = sqrtf(fmaf(gx, gx, fmaf(gy, gy, 1e-8f)));
            float viol = fabsf(mag - 1.0f);
            float msk  = (rv[j] > 0.5f) ? 1.0f : 0.0f;
            lsum = fmaf(viol, msk, lsum);
            lcnt += msk;
        }

        // rotate rows: t <- m, m <- bt
        #pragma unroll
        for (int j = 0; j < 6; j++) { t[j] = m[j]; m[j] = bt[j]; }
    }

    // ---- block reduction ----
    #pragma unroll
    for (int off = 16; off > 0; off >>= 1) {
        lsum += __shfl_down_sync(0xFFFFFFFFu, lsum, off);
        lcnt += __shfl_down_sync(0xFFFFFFFFu, lcnt, off);
    }

    __shared__ float s_sum[8];
    __shared__ float s_cnt[8];
    const int lane = threadIdx.x & 31;
    const int wid  = threadIdx.x >> 5;
    if (lane == 0) { s_sum[wid] = lsum; s_cnt[wid] = lcnt; }
    __syncthreads();

    __shared__ bool s_last;
    if (wid == 0) {
        lsum = (lane < 8) ? s_sum[lane] : 0.0f;
        lcnt = (lane < 8) ? s_cnt[lane] : 0.0f;
        #pragma unroll
        for (int off = 4; off > 0; off >>= 1) {
            lsum += __shfl_down_sync(0xFFFFFFFFu, lsum, off);
            lcnt += __shfl_down_sync(0xFFFFFFFFu, lcnt, off);
        }
        if (lane == 0) {
            g_part[blockIdx.x] = make_float2(lsum, lcnt);
            __threadfence();
            unsigned int prev = atomicAdd(&g_ticket, 1u);
            s_last = (prev == (unsigned int)(nBlocks - 1));
        }
    }
    __syncthreads();

    // ---- last block: reduce partials, write output, reset ticket ----
    if (s_last) {
        float fs = 0.0f, fc = 0.0f;
        for (int i = threadIdx.x; i < nBlocks; i += THREADS) {
            float2 v = g_part[i];
            fs += v.x;
            fc += v.y;
        }
        #pragma unroll
        for (int off = 16; off > 0; off >>= 1) {
            fs += __shfl_down_sync(0xFFFFFFFFu, fs, off);
            fc += __shfl_down_sync(0xFFFFFFFFu, fc, off);
        }
        if (lane == 0) { s_sum[wid] = fs; s_cnt[wid] = fc; }
        __syncthreads();
        if (threadIdx.x == 0) {
            fs = 0.0f; fc = 0.0f;
            #pragma unroll
            for (int i = 0; i < THREADS / 32; i++) { fs += s_sum[i]; fc += s_cnt[i]; }
            out[0] = fs / fmaxf(fc, 1.0f);
            g_ticket = 0;   // reset for next (graph-replayed) call
        }
    }
}

extern "C" void kernel_launch(void* const* d_in, const int* in_sizes, int n_in,
                              void* d_out, int out_size) {
    const float* pred  = (const float*)d_in[0];
    const float* reach = (const float*)d_in[1];
    float* out = (float*)d_out;

    const int total    = in_sizes[0];              // B*H*W
    const int nThreads = (total / W) / ROWS * W4;  // B * STRIPS * W4
    const int nBlocks  = nThreads / THREADS;       // 1024 for B=64

    eik_fused_kernel<<<nBlocks, THREADS>>>(pred, reach, out, nBlocks);
}